// round 3
// baseline (speedup 1.0000x reference)
#include <cuda_runtime.h>
#include <cuda_bf16.h>

// VQ-VAE eval forward for GB300 (sm_103a).
// Round 3 == Round 2 resubmit (container infra failed twice; no bench signal).
// Exact replication of the reference's fp32 ranking pipeline:
//   dist = sqrtf(max((z2 - 2*dot) + e2, 0)), argmin with first-index ties.
// The sqrt quantization (1 ulp of sqrt ~ 4 ulps of d2) creates exact ties that
// jnp.argmin resolves to the lowest index; ranking by -2dot+e2 alone flips
// ~1 row in 32768 (measured round 1: rel_err 7.3e-3 ~ exactly 1 bad row).

#define KC      2048        // codebook size
#define DD      256         // embedding dim
#define BETA_F  0.25f

#define TM 128
#define TN 128
#define TK 16

#define MAXROWS 32768

// ---- scratch (static device globals: no runtime allocation) ----
__device__ float g_e2[KC];
__device__ float g_z2[MAXROWS];
__device__ int   g_idx[MAXROWS];
__device__ int   g_counts[KC];
__device__ float g_partials[MAXROWS];

// ---- packed f32x2 helpers ----
__device__ __forceinline__ unsigned long long pk2(float x, float y) {
    unsigned long long r;
    asm("mov.b64 %0, {%1, %2};" : "=l"(r) : "f"(x), "f"(y));
    return r;
}
__device__ __forceinline__ void fma2(unsigned long long& c,
                                     unsigned long long a,
                                     unsigned long long b) {
    asm("fma.rn.f32x2 %0, %1, %2, %0;" : "+l"(c) : "l"(a), "l"(b));
}
__device__ __forceinline__ float2 upk2(unsigned long long v) {
    float2 r;
    asm("mov.b64 {%0, %1}, %2;" : "=f"(r.x), "=f"(r.y) : "l"(v));
    return r;
}

// ============================================================================
// prep_e2: e2[k] = ||embed[k]||^2 (fp32 pairwise tree), zero histogram.
// grid = KC blocks, 256 threads.
// ============================================================================
__global__ void vq_prep_e2_kernel(const float* __restrict__ W) {
    int row = blockIdx.x;
    int tid = threadIdx.x;
    float w = W[(size_t)row * DD + tid];
    __shared__ float red[256];
    red[tid] = w * w;
    __syncthreads();
    for (int s = 128; s > 0; s >>= 1) {
        if (tid < s) red[tid] += red[tid + s];
        __syncthreads();
    }
    if (tid == 0) {
        g_e2[row] = red[0];
        g_counts[row] = 0;
    }
}

// ============================================================================
// prep_z2: z2[r] = ||z_e[r]||^2 (fp32 pairwise tree). grid = n_rows blocks.
// ============================================================================
__global__ void vq_prep_z2_kernel(const float* __restrict__ Z) {
    int row = blockIdx.x;
    int tid = threadIdx.x;
    float z = Z[(size_t)row * DD + tid];
    __shared__ float red[256];
    red[tid] = z * z;
    __syncthreads();
    for (int s = 128; s > 0; s >>= 1) {
        if (tid < s) red[tid] += red[tid + s];
        __syncthreads();
    }
    if (tid == 0) g_z2[row] = red[0];
}

// ============================================================================
// argmin: per 128-row CTA, stream all 2048 codes in 128-wide tiles,
// f32x2-packed fp32 dot products; epilogue replicates the reference ranking:
//   u = (z2 - 2*dot) + e2 ; dist = sqrtf(max(u,0)) ; argmin, first index wins.
// 256 threads: 16x16 thread grid, 8x8 microtile each.
// ============================================================================
__global__ __launch_bounds__(256, 2)
void vq_argmin_kernel(const float* __restrict__ Z, const float* __restrict__ W) {
    __shared__ float As[TK][TM + 8];
    __shared__ float Bs[TK][TN + 8];

    const int tid = threadIdx.x;
    const int tm = tid >> 4;     // 0..15 -> rows tm*8..tm*8+7
    const int tn = tid & 15;     // 0..15 -> cols tn*8..tn*8+7
    const int rowBase = blockIdx.x * TM;

    float best[8];
    int   bidx[8];
#pragma unroll
    for (int i = 0; i < 8; ++i) { best[i] = 3.4e38f; bidx[i] = 0; }

    float z2r[8];
#pragma unroll
    for (int i = 0; i < 8; ++i) z2r[i] = g_z2[rowBase + tm * 8 + i];

    for (int nt = 0; nt < KC / TN; ++nt) {
        const int colBase = nt * TN;

        unsigned long long acc2[8][4];   // [row][col-pair], f32x2 packed
#pragma unroll
        for (int i = 0; i < 8; ++i)
#pragma unroll
            for (int jp = 0; jp < 4; ++jp) acc2[i][jp] = 0ull;

        for (int kt = 0; kt < DD / TK; ++kt) {
            __syncthreads();
#pragma unroll
            for (int u = 0; u < 2; ++u) {
                int v = tid * 2 + u;      // 0..511
                int m = v >> 2;           // 0..127
                int c = v & 3;            // k offset c*4
                const float4 za = *(const float4*)&Z[(size_t)(rowBase + m) * DD + kt * TK + c * 4];
                As[c * 4 + 0][m] = za.x; As[c * 4 + 1][m] = za.y;
                As[c * 4 + 2][m] = za.z; As[c * 4 + 3][m] = za.w;
                const float4 wb = *(const float4*)&W[(size_t)(colBase + m) * DD + kt * TK + c * 4];
                Bs[c * 4 + 0][m] = wb.x; Bs[c * 4 + 1][m] = wb.y;
                Bs[c * 4 + 2][m] = wb.z; Bs[c * 4 + 3][m] = wb.w;
            }
            __syncthreads();

#pragma unroll
            for (int kk = 0; kk < TK; ++kk) {
                float a[8];
                *(float4*)&a[0] = *(const float4*)&As[kk][tm * 8];
                *(float4*)&a[4] = *(const float4*)&As[kk][tm * 8 + 4];
                unsigned long long b2[4];
                const unsigned long long* bp =
                    (const unsigned long long*)&Bs[kk][tn * 8];
                b2[0] = bp[0]; b2[1] = bp[1]; b2[2] = bp[2]; b2[3] = bp[3];
#pragma unroll
                for (int i = 0; i < 8; ++i) {
                    unsigned long long a2 = pk2(a[i], a[i]);
                    fma2(acc2[i][0], a2, b2[0]);
                    fma2(acc2[i][1], a2, b2[1]);
                    fma2(acc2[i][2], a2, b2[2]);
                    fma2(acc2[i][3], a2, b2[3]);
                }
            }
        }

        // epilogue: replicate reference fp32 pipeline exactly.
        // (2*dot is exact, so "z2 - 2*dot" has a single unambiguous rounding
        // whether or not ptxas contracts it to an FMA.)
        float e2v[8];
        *(float4*)&e2v[0] = *(const float4*)&g_e2[colBase + tn * 8];
        *(float4*)&e2v[4] = *(const float4*)&g_e2[colBase + tn * 8 + 4];
#pragma unroll
        for (int i = 0; i < 8; ++i) {
#pragma unroll
            for (int jp = 0; jp < 4; ++jp) {
                float2 d = upk2(acc2[i][jp]);
                int k0 = colBase + tn * 8 + jp * 2;
                float u0 = (z2r[i] - 2.0f * d.x) + e2v[jp * 2];
                float u1 = (z2r[i] - 2.0f * d.y) + e2v[jp * 2 + 1];
                float s0 = sqrtf(fmaxf(u0, 0.0f));
                float s1 = sqrtf(fmaxf(u1, 0.0f));
                // ascending k + strict < == first-index-wins on exact ties
                if (s0 < best[i]) { best[i] = s0; bidx[i] = k0; }
                if (s1 < best[i]) { best[i] = s1; bidx[i] = k0 + 1; }
            }
        }
    }

    // cross-thread reduce over 16 lanes (same tm group is 16 contiguous lanes
    // within one warp); ties -> lowest index.
#pragma unroll
    for (int i = 0; i < 8; ++i) {
        float s = best[i];
        int b = bidx[i];
#pragma unroll
        for (int off = 8; off > 0; off >>= 1) {
            float so = __shfl_xor_sync(0xffffffffu, s, off);
            int   bo = __shfl_xor_sync(0xffffffffu, b, off);
            if (so < s || (so == s && bo < b)) { s = so; b = bo; }
        }
        if (tn == 0) g_idx[rowBase + tm * 8 + i] = b;
    }
}

// ============================================================================
// gather: z_q_st = z_e + (embed[idx] - z_e), MSE partial per row, histogram.
// grid = n_rows blocks, 256 threads.
// ============================================================================
__global__ void vq_gather_kernel(const float* __restrict__ Z,
                                 const float* __restrict__ W,
                                 float* __restrict__ out,
                                 int n_rows, int write_idx) {
    int row = blockIdx.x;
    int tid = threadIdx.x;
    int k = g_idx[row];
    float ze = Z[(size_t)row * DD + tid];
    float w  = W[(size_t)k * DD + tid];
    float diff = w - ze;
    out[(size_t)row * DD + tid] = ze + diff;   // straight-through forward value

    __shared__ float red[256];
    red[tid] = diff * diff;
    __syncthreads();
    for (int s = 128; s > 0; s >>= 1) {
        if (tid < s) red[tid] += red[tid + s];
        __syncthreads();
    }
    if (tid == 0) {
        g_partials[row] = red[0];
        atomicAdd(&g_counts[k], 1);            // int atomic: deterministic
        if (write_idx)
            out[(size_t)n_rows * DD + 1 + row] = (float)k;
    }
}

// ============================================================================
// loss: deterministic fixed-order reductions; vq_loss = (1+beta)*MSE - 0.01*ppl
// ============================================================================
__global__ void vq_loss_kernel(float* __restrict__ out, int n_rows, int write_loss) {
    int tid = threadIdx.x;
    float s = 0.0f;
    for (int i = tid; i < n_rows; i += 1024) s += g_partials[i];
    float h = 0.0f;
    for (int k = tid; k < KC; k += 1024) {
        float p = (float)g_counts[k] / (float)n_rows;
        h -= p * logf(p + 1e-10f);
    }
    __shared__ float rs[1024];
    __shared__ float rh[1024];
    rs[tid] = s; rh[tid] = h;
    __syncthreads();
    for (int st = 512; st > 0; st >>= 1) {
        if (tid < st) { rs[tid] += rs[tid + st]; rh[tid] += rh[tid + st]; }
        __syncthreads();
    }
    if (tid == 0 && write_loss) {
        float mse = rs[0] / ((float)n_rows * (float)DD);
        float perplexity = expf(rh[0]);
        out[(size_t)n_rows * DD] = (1.0f + BETA_F) * mse - 0.01f * perplexity;
    }
}

// ============================================================================
extern "C" void kernel_launch(void* const* d_in, const int* in_sizes, int n_in,
                              void* d_out, int out_size) {
    (void)n_in;
    const float* Z = (const float*)d_in[0];   // z_e  [8,4096,256] fp32
    const float* W = (const float*)d_in[1];   // embed [2048,256] fp32
    float* out = (float*)d_out;

    int D = in_sizes[1] / KC;                  // 256
    int n_rows = in_sizes[0] / D;              // 32768
    long long nzq = (long long)n_rows * D;
    int write_loss = (out_size >= nzq + 1) ? 1 : 0;
    int write_idx  = (out_size >= nzq + 1 + n_rows) ? 1 : 0;

    vq_prep_e2_kernel<<<KC, 256>>>(W);
    vq_prep_z2_kernel<<<n_rows, 256>>>(Z);
    vq_argmin_kernel<<<n_rows / TM, 256>>>(Z, W);
    vq_gather_kernel<<<n_rows, 256>>>(Z, W, out, n_rows, write_idx);
    vq_loss_kernel<<<1, 1024>>>(out, n_rows, write_loss);
}

// round 6
// speedup vs baseline: 1.9838x; 1.9838x over previous
#include <cuda_runtime.h>
#include <cuda_bf16.h>
#include <cstdint>

// VQ-VAE eval forward for GB300 (sm_103a die, but harness targets sm_103 base
// ISA -> no tcgen05). Round 6: base-ISA tensor cores via mma.sync.m16n8k16
// bf16 computing APPROXIMATE scores; per-row top-8 candidate band (margin
// 23-sigma of the bf16 error); exact fp32 re-rank of candidates reproduces the
// reference ranking pipeline bit-compatibly (proven in round 3).

#define KC      2048
#define DD      256
#define BETA_F  0.25f
#define MAXROWS 32768
#define MARGIN  0.05f

#define TILE_M  128
#define TILE_N  128
#define NTILES  (KC / TILE_N)     // 16

// smem layout (bytes)
#define APITCH  264               // bf16 units per A row (128-row x 256-k tile, +8 pad)
#define BPITCH  136               // bf16 units per B row (128-n x 128-k tile, +8 pad)
#define OFF_A   0
#define ABYTES  (TILE_M * APITCH * 2)              // 67584
#define OFF_B   ABYTES
#define BBYTES  (TILE_N * BPITCH * 2)              // 34816
#define OFF_US  (OFF_B + 2 * BBYTES)               // 137216
#define USBYTES (128 * 128 * 4)                    // 65536
#define OFF_E2  (OFF_US + USBYTES)                 // 202752
#define SMEM_TOTAL (OFF_E2 + 512)                  // 203264

// ---- static device scratch ----
__device__ float          g_e2[KC];
__device__ __nv_bfloat16  g_Wbf[KC * DD];
__device__ int            g_cand[MAXROWS * 8];
__device__ int            g_ncand[MAXROWS];
__device__ int            g_counts[KC];
__device__ float          g_partials[MAXROWS];

// ============================================================================
// helpers
// ============================================================================
__device__ __forceinline__ uint32_t smem_u32(const void* p) {
    uint32_t a;
    asm("{ .reg .u64 t; cvta.to.shared.u64 t, %1; cvt.u32.u64 %0, t; }" : "=r"(a) : "l"(p));
    return a;
}

__device__ __forceinline__ void ldsm_x4(uint32_t& r0, uint32_t& r1, uint32_t& r2,
                                        uint32_t& r3, uint32_t addr) {
    asm volatile("ldmatrix.sync.aligned.m8n8.x4.shared.b16 {%0,%1,%2,%3}, [%4];"
                 : "=r"(r0), "=r"(r1), "=r"(r2), "=r"(r3) : "r"(addr));
}

__device__ __forceinline__ void mma16816(float* c, const uint32_t* a, const uint32_t* b) {
    asm volatile("mma.sync.aligned.m16n8k16.row.col.f32.bf16.bf16.f32 "
                 "{%0,%1,%2,%3}, {%4,%5,%6,%7}, {%8,%9}, {%0,%1,%2,%3};"
                 : "+f"(c[0]), "+f"(c[1]), "+f"(c[2]), "+f"(c[3])
                 : "r"(a[0]), "r"(a[1]), "r"(a[2]), "r"(a[3]), "r"(b[0]), "r"(b[1]));
}

// bank swizzle for the score buffer: 5-bit bijection of the row injected into
// the column's bank bits -> conflict-free fragment writes AND per-row scans.
__device__ __forceinline__ int fswz(int r) {
    return (r & 1) | (((r >> 3) & 3) << 1) | (((r >> 1) & 3) << 3);
}

// ============================================================================
// prep: e2[k] = ||W[k]||^2 (fp32 tree, round-3-proven order), W -> bf16, zero hist
// ============================================================================
__global__ void vq_prep_kernel(const float* __restrict__ W) {
    int row = blockIdx.x, tid = threadIdx.x;
    float w = W[(size_t)row * DD + tid];
    g_Wbf[(size_t)row * DD + tid] = __float2bfloat16_rn(w);
    __shared__ float red[256];
    red[tid] = w * w;
    __syncthreads();
    for (int s = 128; s > 0; s >>= 1) {
        if (tid < s) red[tid] += red[tid + s];
        __syncthreads();
    }
    if (tid == 0) { g_e2[row] = red[0]; g_counts[row] = 0; }
}

// ============================================================================
// phase 1: HMMA approx-score GEMM + per-row top-8 candidate band.
// 256 threads (8 warps: 4x2 over 128x128), grid = n_rows/128.
// ============================================================================
__global__ __launch_bounds__(256)
void vq_hmma_kernel(const float* __restrict__ Z) {
    extern __shared__ char smem[];
    const uint32_t sb = smem_u32(smem);
    const int tid = threadIdx.x;
    const int lane = tid & 31, wid = tid >> 5;
    const int wm = wid & 3, wn = wid >> 2;
    const int grp = lane >> 3, lr = lane & 7;
    const int rowBase = blockIdx.x * TILE_M;
    float* Us = (float*)(smem + OFF_US);
    float* e2s = (float*)(smem + OFF_E2);

    // ---- ldmatrix lane addresses ----
    uint32_t aAddr[2];
#pragma unroll
    for (int f = 0; f < 2; ++f) {
        int r = wm * 32 + f * 16 + (grp & 1) * 8 + lr;
        int kof = (grp >> 1) * 8;
        aAddr[f] = sb + OFF_A + (uint32_t)(r * APITCH + kof) * 2u;
    }
    uint32_t bAddr[4];
#pragma unroll
    for (int p = 0; p < 4; ++p) {
        int n = wn * 64 + p * 16 + (grp >> 1) * 8 + lr;
        int kof = (grp & 1) * 8;
        bAddr[p] = sb + OFF_B + (uint32_t)(n * BPITCH + kof) * 2u;
    }

    // ---- load A tile: 128 rows x 256 dims fp32 -> bf16 smem ----
    {
        int r = tid >> 1, hf = tid & 1;
        const float4* src = (const float4*)(Z + (size_t)(rowBase + r) * DD + hf * 128);
        __nv_bfloat162* dst = (__nv_bfloat162*)(smem + OFF_A);
        int base = r * (APITCH / 2) + hf * 64;
#pragma unroll 8
        for (int j = 0; j < 32; ++j) {
            float4 v = src[j];
            dst[base + j * 2]     = __float22bfloat162_rn(make_float2(v.x, v.y));
            dst[base + j * 2 + 1] = __float22bfloat162_rn(make_float2(v.z, v.w));
        }
    }

    // ---- top-8 state (ascending u; u0 = min) ----
    float u0 = 3.4e38f, u1 = 3.4e38f, u2 = 3.4e38f, u3 = 3.4e38f,
          u4 = 3.4e38f, u5 = 3.4e38f, u6 = 3.4e38f, u7 = 3.4e38f;
    int   k0 = 0, k1 = 0, k2 = 0, k3 = 0, k4 = 0, k5 = 0, k6 = 0, k7 = 0;
    const int myf = fswz(tid & 127);

    float acc[2][8][4];
    uint4 rb[8];

    // prefetch B tile 0
    {
        int n = tid >> 1, hf = tid & 1;
        const uint4* src = (const uint4*)g_Wbf + ((size_t)n * DD + hf * 64) / 8;
#pragma unroll
        for (int j = 0; j < 8; ++j) rb[j] = src[j];
    }

    for (int t = 0; t < 2 * NTILES; ++t) {
        const int nt = t >> 1, kt = t & 1, buf = t & 1;
        const uint32_t bufOff = (uint32_t)buf * BBYTES;

        __syncthreads();                       // prior readers of Bs[buf] done
        {   // store prefetched regs -> Bs[buf]
            int n = tid >> 1, hf = tid & 1;
            uint4* dst = (uint4*)(smem + OFF_B + bufOff) + (n * (BPITCH / 8) + hf * 8);
#pragma unroll
            for (int j = 0; j < 8; ++j) dst[j] = rb[j];
        }
        if (kt == 0 && tid < 128) e2s[tid] = g_e2[nt * 128 + tid];
        if (t + 1 < 2 * NTILES) {              // prefetch next tile
            int tn = t + 1;
            int n = tid >> 1, hf = tid & 1;
            const uint4* src = (const uint4*)g_Wbf +
                ((size_t)((tn >> 1) * 128 + n) * DD + (tn & 1) * 128 + hf * 64) / 8;
#pragma unroll
            for (int j = 0; j < 8; ++j) rb[j] = src[j];
        }
        __syncthreads();                       // Bs[buf] visible

        if (kt == 0) {
#pragma unroll
            for (int mf = 0; mf < 2; ++mf)
#pragma unroll
                for (int nf = 0; nf < 8; ++nf)
#pragma unroll
                    for (int c = 0; c < 4; ++c) acc[mf][nf][c] = 0.0f;
        }

#pragma unroll
        for (int ks = 0; ks < 8; ++ks) {
            uint32_t a[2][4], b[8][2];
            ldsm_x4(a[0][0], a[0][1], a[0][2], a[0][3],
                    aAddr[0] + (uint32_t)(kt * 128 + ks * 16) * 2u);
            ldsm_x4(a[1][0], a[1][1], a[1][2], a[1][3],
                    aAddr[1] + (uint32_t)(kt * 128 + ks * 16) * 2u);
#pragma unroll
            for (int p = 0; p < 4; ++p)
                ldsm_x4(b[2 * p][0], b[2 * p][1], b[2 * p + 1][0], b[2 * p + 1][1],
                        bAddr[p] + bufOff + (uint32_t)(ks * 16) * 2u);
#pragma unroll
            for (int mf = 0; mf < 2; ++mf)
#pragma unroll
                for (int nf = 0; nf < 8; ++nf)
                    mma16816(acc[mf][nf], a[mf], b[nf]);
        }

        if (kt == 1) {
            // ---- stage u = e2 - 2*d into swizzled smem ----
#pragma unroll
            for (int mf = 0; mf < 2; ++mf) {
                int r0 = wm * 32 + mf * 16 + (lane >> 2);
#pragma unroll
                for (int nf = 0; nf < 8; ++nf) {
                    int c0 = wn * 64 + nf * 8 + 2 * (lane & 3);
                    float e0 = e2s[c0], e1 = e2s[c0 + 1];
                    Us[r0 * 128 + ((c0)     ^ fswz(r0))] = fmaf(-2.0f, acc[mf][nf][0], e0);
                    Us[r0 * 128 + ((c0 + 1) ^ fswz(r0))] = fmaf(-2.0f, acc[mf][nf][1], e1);
                    int r1 = r0 + 8;
                    Us[r1 * 128 + ((c0)     ^ fswz(r1))] = fmaf(-2.0f, acc[mf][nf][2], e0);
                    Us[r1 * 128 + ((c0 + 1) ^ fswz(r1))] = fmaf(-2.0f, acc[mf][nf][3], e1);
                }
            }
            __syncthreads();
            if (tid < 128) {
                const float* urow = Us + tid * 128;
                int kbase = nt * 128;
#pragma unroll 4
                for (int c = 0; c < 128; ++c) {
                    float u = urow[c ^ myf];
                    if (u < u7) {
                        u7 = u; k7 = kbase + c;
                        if (u7 < u6) { float tu = u6; u6 = u7; u7 = tu; int tk = k6; k6 = k7; k7 = tk; }
                        if (u6 < u5) { float tu = u5; u5 = u6; u6 = tu; int tk = k5; k5 = k6; k6 = tk; }
                        if (u5 < u4) { float tu = u4; u4 = u5; u5 = tu; int tk = k4; k4 = k5; k5 = tk; }
                        if (u4 < u3) { float tu = u3; u3 = u4; u4 = tu; int tk = k3; k3 = k4; k4 = tk; }
                        if (u3 < u2) { float tu = u2; u2 = u3; u3 = tu; int tk = k2; k2 = k3; k3 = tk; }
                        if (u2 < u1) { float tu = u1; u1 = u2; u2 = tu; int tk = k1; k1 = k2; k2 = tk; }
                        if (u1 < u0) { float tu = u0; u0 = u1; u1 = tu; int tk = k0; k0 = k1; k1 = tk; }
                    }
                }
            }
            // scan completes before this thread's next __syncthreads (top of loop)
        }
    }

    if (tid < 128) {
        int row = rowBase + tid;
        float thr = u0 + MARGIN;
        int cnt = 1 + (u1 <= thr) + (u2 <= thr) + (u3 <= thr) + (u4 <= thr)
                    + (u5 <= thr) + (u6 <= thr) + (u7 <= thr);
        g_cand[row * 8 + 0] = k0; g_cand[row * 8 + 1] = k1;
        g_cand[row * 8 + 2] = k2; g_cand[row * 8 + 3] = k3;
        g_cand[row * 8 + 4] = k4; g_cand[row * 8 + 5] = k5;
        g_cand[row * 8 + 6] = k6; g_cand[row * 8 + 7] = k7;
        g_ncand[row] = (cnt == 8) ? 9 : cnt;   // 9 = overflow sentinel
    }
}

// ============================================================================
// phase 2: exact re-rank of candidates (reference fp32 ranking pipeline,
// lexicographic (s,k) min == first-index tie-break) fused with gather/MSE/hist.
// warp per row; block 256 -> 8 rows; grid = n_rows/8.
// ============================================================================
__global__ __launch_bounds__(256)
void vq_refine_gather_kernel(const float* __restrict__ Z, const float* __restrict__ W,
                             float* __restrict__ out, int n_rows, int write_idx) {
    const int lane = threadIdx.x & 31;
    const int row = blockIdx.x * 8 + (threadIdx.x >> 5);

    float4 z0 = *(const float4*)&Z[(size_t)row * DD + lane * 8];
    float4 z1 = *(const float4*)&Z[(size_t)row * DD + lane * 8 + 4];
    float p = z0.x * z0.x + z0.y * z0.y + z0.z * z0.z + z0.w * z0.w
            + z1.x * z1.x + z1.y * z1.y + z1.z * z1.z + z1.w * z1.w;
#pragma unroll
    for (int off = 16; off > 0; off >>= 1) p += __shfl_xor_sync(0xffffffffu, p, off);
    const float z2 = p;

    int nc = g_ncand[row];
    float sbest = 3.4e38f;
    int kbest = 0;
    int iters = (nc <= 8) ? nc : KC;
    for (int i = 0; i < iters; ++i) {
        int k = (nc <= 8) ? g_cand[row * 8 + i] : i;
        float4 w0 = *(const float4*)&W[(size_t)k * DD + lane * 8];
        float4 w1 = *(const float4*)&W[(size_t)k * DD + lane * 8 + 4];
        float d = z0.x * w0.x + z0.y * w0.y + z0.z * w0.z + z0.w * w0.w
                + z1.x * w1.x + z1.y * w1.y + z1.z * w1.z + z1.w * w1.w;
#pragma unroll
        for (int off = 16; off > 0; off >>= 1) d += __shfl_xor_sync(0xffffffffu, d, off);
        float u = (z2 - 2.0f * d) + g_e2[k];
        float s = sqrtf(fmaxf(u, 0.0f));
        if (s < sbest || (s == sbest && k < kbest)) { sbest = s; kbest = k; }
    }

    // ---- gather + MSE partial + histogram ----
    float4 w0 = *(const float4*)&W[(size_t)kbest * DD + lane * 8];
    float4 w1 = *(const float4*)&W[(size_t)kbest * DD + lane * 8 + 4];
    float d0 = w0.x - z0.x, d1 = w0.y - z0.y, d2 = w0.z - z0.z, d3 = w0.w - z0.w;
    float d4 = w1.x - z1.x, d5 = w1.y - z1.y, d6 = w1.z - z1.z, d7 = w1.w - z1.w;
    float4 o0 = make_float4(z0.x + d0, z0.y + d1, z0.z + d2, z0.w + d3);
    float4 o1 = make_float4(z1.x + d4, z1.y + d5, z1.z + d6, z1.w + d7);
    *(float4*)&out[(size_t)row * DD + lane * 8]     = o0;
    *(float4*)&out[(size_t)row * DD + lane * 8 + 4] = o1;
    float sq = d0 * d0 + d1 * d1 + d2 * d2 + d3 * d3
             + d4 * d4 + d5 * d5 + d6 * d6 + d7 * d7;
#pragma unroll
    for (int off = 16; off > 0; off >>= 1) sq += __shfl_xor_sync(0xffffffffu, sq, off);
    if (lane == 0) {
        g_partials[row] = sq;
        atomicAdd(&g_counts[kbest], 1);
        if (write_idx) out[(size_t)n_rows * DD + 1 + row] = (float)kbest;
    }
}

// ============================================================================
// loss: deterministic reductions; vq_loss = (1+beta)*MSE - 0.01*perplexity
// ============================================================================
__global__ void vq_loss_kernel(float* __restrict__ out, int n_rows, int write_loss) {
    int tid = threadIdx.x;
    float s = 0.0f;
    for (int i = tid; i < n_rows; i += 1024) s += g_partials[i];
    float h = 0.0f;
    for (int k = tid; k < KC; k += 1024) {
        float p = (float)g_counts[k] / (float)n_rows;
        h -= p * logf(p + 1e-10f);
    }
    __shared__ float rs[1024];
    __shared__ float rh[1024];
    rs[tid] = s; rh[tid] = h;
    __syncthreads();
    for (int st = 512; st > 0; st >>= 1) {
        if (tid < st) { rs[tid] += rs[tid + st]; rh[tid] += rh[tid + st]; }
        __syncthreads();
    }
    if (tid == 0 && write_loss) {
        float mse = rs[0] / ((float)n_rows * (float)DD);
        float perplexity = expf(rh[0]);
        out[(size_t)n_rows * DD] = (1.0f + BETA_F) * mse - 0.01f * perplexity;
    }
}

// ============================================================================
extern "C" void kernel_launch(void* const* d_in, const int* in_sizes, int n_in,
                              void* d_out, int out_size) {
    (void)n_in;
    const float* Z = (const float*)d_in[0];   // z_e  [8,4096,256] fp32
    const float* W = (const float*)d_in[1];   // embed [2048,256] fp32
    float* out = (float*)d_out;

    int D = in_sizes[1] / KC;                  // 256
    int n_rows = in_sizes[0] / D;              // 32768
    long long nzq = (long long)n_rows * D;
    int write_loss = (out_size >= nzq + 1) ? 1 : 0;
    int write_idx  = (out_size >= nzq + 1 + n_rows) ? 1 : 0;

    cudaFuncSetAttribute(vq_hmma_kernel,
                         cudaFuncAttributeMaxDynamicSharedMemorySize, SMEM_TOTAL);

    vq_prep_kernel<<<KC, 256>>>(W);
    vq_hmma_kernel<<<n_rows / TILE_M, 256, SMEM_TOTAL>>>(Z);
    vq_refine_gather_kernel<<<n_rows / 8, 256>>>(Z, W, out, n_rows, write_idx);
    vq_loss_kernel<<<1, 1024>>>(out, n_rows, write_loss);
}